// round 16
// baseline (speedup 1.0000x reference)
#include <cuda_runtime.h>
#include <cuda_fp16.h>
#include <cstdint>

#define CONST __restrict__
using f16 = __half;

static constexpr int B_  = 1024;
static constexpr int KO  = 10;
static constexpr int D_  = 32;
static constexpr int H_  = 512;
static constexpr int NN  = B_ * KO;     // 10240
static constexpr int EPN = KO - 1;      // 9
static constexpr int NE  = NN * EPN;    // 92160
static constexpr float EPS = 1e-5f;
static constexpr int K4P = 576;

static constexpr int NSLICE = 2;
static constexpr int ESL = NE / NSLICE;   // 46080
static constexpr int NSL = NN / NSLICE;   // 5120

// ---------------- scratch ----------------
__device__ __align__(16) f16 gST[NN * 64];
__device__ float gP[NN * H_], gQ[NN * H_];
__device__ __align__(16) f16 gE[(size_t)NE * H_];
__device__ __align__(16) f16 gH2[(size_t)NE * H_];
__device__ __align__(16) f16 gS [NN * H_];
__device__ __align__(16) f16 gA4[NN * K4P];
__device__ __align__(16) f16 gN1[NN * H_];
__device__ float gN2r[NN * H_];

__device__ __align__(16) f16 gW0[1024 * 64];
__device__ __align__(16) f16 gW2[H_ * H_];
__device__ __align__(16) f16 gW3[H_ * H_];
__device__ __align__(16) f16 gW4[H_ * K4P];
__device__ __align__(16) f16 gW5[H_ * H_];

// ---------------- helpers ----------------
__device__ __forceinline__ uint32_t s2u(const void* p) {
    uint32_t a;
    asm("{ .reg .u64 t; cvta.to.shared.u64 t, %1; cvt.u32.u64 %0, t; }" : "=r"(a) : "l"(p));
    return a;
}
__device__ __forceinline__ void cp16(uint32_t s, const void* g) {
    asm volatile("cp.async.cg.shared.global [%0], [%1], 16;" :: "r"(s), "l"(g));
}
__device__ __forceinline__ void ldsm4(uint32_t* r, uint32_t a) {
    asm volatile("ldmatrix.sync.aligned.m8n8.x4.shared.b16 {%0,%1,%2,%3}, [%4];"
        : "=r"(r[0]), "=r"(r[1]), "=r"(r[2]), "=r"(r[3]) : "r"(a));
}
__device__ __forceinline__ void mma_f16(float* c, const uint32_t* a, uint32_t b0, uint32_t b1) {
    asm("mma.sync.aligned.m16n8k16.row.col.f32.f16.f16.f32 "
        "{%0,%1,%2,%3}, {%4,%5,%6,%7}, {%8,%9}, {%0,%1,%2,%3};\n"
        : "+f"(c[0]), "+f"(c[1]), "+f"(c[2]), "+f"(c[3])
        : "r"(a[0]), "r"(a[1]), "r"(a[2]), "r"(a[3]), "r"(b0), "r"(b1));
}
__device__ __forceinline__ uint32_t pkh(float a, float b) {
    __half2 t; t.x = __float2half_rn(a); t.y = __float2half_rn(b);
    return *(uint32_t*)&t;
}

// ---------------- shared device bodies ----------------
__device__ __forceinline__ void esplit_do8(int e, int cg)
{
    int node = e / EPN;
    int jj = e - node * EPN;
    int i = node % KO;
    int j = jj + (jj >= i ? 1 : 0);
    int cn = node - i + j;
    float4 p0 = *(const float4*)(gP + (size_t)node * H_ + cg);
    float4 p1 = *(const float4*)(gP + (size_t)node * H_ + cg + 4);
    float4 q0 = *(const float4*)(gQ + (size_t)cn * H_ + cg);
    float4 q1 = *(const float4*)(gQ + (size_t)cn * H_ + cg + 4);
    f16 o[8];
    o[0] = __float2half_rn(fmaxf(p0.x + q0.x, 0.f));
    o[1] = __float2half_rn(fmaxf(p0.y + q0.y, 0.f));
    o[2] = __float2half_rn(fmaxf(p0.z + q0.z, 0.f));
    o[3] = __float2half_rn(fmaxf(p0.w + q0.w, 0.f));
    o[4] = __float2half_rn(fmaxf(p1.x + q1.x, 0.f));
    o[5] = __float2half_rn(fmaxf(p1.y + q1.y, 0.f));
    o[6] = __float2half_rn(fmaxf(p1.z + q1.z, 0.f));
    o[7] = __float2half_rn(fmaxf(p1.w + q1.w, 0.f));
    *(uint4*)(gE + (size_t)e * H_ + cg) = *(const uint4*)o;
}

// one warp handles node n (LN+relu over 9 edge rows, sum -> gS)
__device__ __forceinline__ void ln_sum_node(int n, int lane,
                                            const float* CONST g, const float* CONST bt)
{
    float G[16], Bt[16], acc[16];
    #pragma unroll
    for (int j = 0; j < 2; j++) {
        const int cb = (lane + 32 * j) * 8;
        #pragma unroll
        for (int u = 0; u < 8; u++) {
            G[j * 8 + u] = g[cb + u];
            Bt[j * 8 + u] = bt[cb + u];
            acc[j * 8 + u] = 0.f;
        }
    }
    for (int e = 0; e < EPN; e++) {
        const f16* rp = gH2 + (size_t)(n * EPN + e) * H_;
        float v[16];
        float s = 0.f, sq = 0.f;
        #pragma unroll
        for (int j = 0; j < 2; j++) {
            uint4 raw = *(const uint4*)(rp + (lane + 32 * j) * 8);
            const __half2* h2 = (const __half2*)&raw;
            #pragma unroll
            for (int p = 0; p < 4; p++) {
                float2 f2 = __half22float2(h2[p]);
                v[j * 8 + p * 2]     = f2.x;
                v[j * 8 + p * 2 + 1] = f2.y;
            }
        }
        #pragma unroll
        for (int u = 0; u < 16; u++) { s += v[u]; sq += v[u] * v[u]; }
        #pragma unroll
        for (int o = 16; o > 0; o >>= 1) {
            s  += __shfl_xor_sync(0xffffffff, s, o);
            sq += __shfl_xor_sync(0xffffffff, sq, o);
        }
        const float mean = s * (1.f / 512.f);
        const float rstd = rsqrtf(sq * (1.f / 512.f) - mean * mean + EPS);
        #pragma unroll
        for (int u = 0; u < 16; u++)
            acc[u] += fmaxf((v[u] - mean) * rstd * G[u] + Bt[u], 0.f);
    }
    #pragma unroll
    for (int j = 0; j < 2; j++) {
        const int cb = (lane + 32 * j) * 8;
        uint4 o4;
        o4.x = pkh(acc[j * 8 + 0], acc[j * 8 + 1]);
        o4.y = pkh(acc[j * 8 + 2], acc[j * 8 + 3]);
        o4.z = pkh(acc[j * 8 + 4], acc[j * 8 + 5]);
        o4.w = pkh(acc[j * 8 + 6], acc[j * 8 + 7]);
        *(uint4*)(gS + (size_t)n * H_ + cb) = o4;
    }
}

// ---------------- merged prep ----------------
static constexpr int PREP_N = 1425408;

__global__ void prep_all(const float* CONST ew1, const float* CONST ew2,
                         const float* CONST ew3, const float* CONST nw1,
                         const float* CONST nw2, const float* CONST states)
{
    int idx = blockIdx.x * 256 + threadIdx.x;
    if (idx >= PREP_N) return;
    if (idx < 32768) {
        int k = idx & 31, n = idx >> 5;
        int sr = (n < 512) ? k : 32 + k;
        int sn = (n < 512) ? n : n - 512;
        gW0[n * 64 + k] = __float2half_rn(ew1[(size_t)sr * H_ + sn]);
    } else if (idx < 294912) {
        int i2 = idx - 32768;
        int k = i2 & 511, n = i2 >> 9;
        gW2[i2] = __float2half_rn(ew2[(size_t)k * H_ + n]);
    } else if (idx < 557056) {
        int i2 = idx - 294912;
        int k = i2 & 511, n = i2 >> 9;
        gW3[i2] = __float2half_rn(ew3[(size_t)k * H_ + n]);
    } else if (idx < 835584) {
        int i2 = idx - 557056;
        int k = i2 % 544, n = i2 / 544;
        int sr = (k >= 32) ? k + 4 : k;
        gW4[n * K4P + k] = __float2half_rn(nw1[(size_t)sr * H_ + n]);
    } else if (idx < 1097728) {
        int i2 = idx - 835584;
        int k = i2 & 511, n = i2 >> 9;
        gW5[i2] = __float2half_rn(nw2[(size_t)k * H_ + n]);
    } else {
        int i2 = idx - 1097728;
        int r = i2 >> 5, c = i2 & 31;
        f16 h = __float2half_rn(states[i2]);
        gST[r * 64 + c] = h;
        gA4[r * K4P + c] = h;
    }
}

// ---------------- standalone esplit (slice 0) ----------------
__global__ __launch_bounds__(256) void esplit(int edgeOff)
{
    int gi = blockIdx.x * 256 + threadIdx.x;
    esplit_do8(edgeOff + (gi >> 6), (gi & 63) * 8);
}

// ---------------- standalone ln_sum (slice 1) ----------------
__global__ __launch_bounds__(256)
void ln_sum_k(const float* CONST g, const float* CONST bt, int nodeOff)
{
    const int warp = threadIdx.x >> 5, lane = threadIdx.x & 31;
    ln_sum_node(nodeOff + blockIdx.x * 8 + warp, lane, g, bt);
}

// ---------------- fp16 mma GEMM (R13 config) + optional fused side blocks ----------------
static constexpr int LDP = 40;
static constexpr int SZA = 128 * LDP * 2;    // 10240 B
static constexpr int STG = 2 * SZA;          // 20480 B per stage
static constexpr int STAGES = 4;
static constexpr int SMEM_SZ = STAGES * STG; // 81920 B

// sideKind: 0 none, 1 esplit (16 edges/block, 32 cols/thread), 2 ln_sum (8 nodes/block)
template <int MODE>
__global__ __launch_bounds__(256, 2)
void tg(const f16* CONST A_, const f16* CONST W_,
        const float* CONST bias, const int* CONST act,
        const float* CONST nw1full, int rowOff,
        int nMainRows, int sideKind, int sideOff,
        const float* CONST sideG, const float* CONST sideBt)
{
    // -------- side-block roles (appended rows) --------
    if ((int)blockIdx.y >= nMainRows) {
        const int sb = ((int)blockIdx.y - nMainRows) * 4 + (int)blockIdx.x;
        const int t = threadIdx.x;
        if (sideKind == 1) {
            const int e = sideOff + sb * 16 + (t >> 4);
            const int cb = (t & 15) * 32;
            #pragma unroll
            for (int u = 0; u < 32; u += 8) esplit_do8(e, cb + u);
        } else {
            ln_sum_node(sideOff + sb * 8 + (t >> 5), t & 31, sideG, sideBt);
        }
        return;
    }

    constexpr int KT     = (MODE == 0) ? 32 : (MODE == 4 ? 544 : 512);
    constexpr int STRIDE = (MODE == 0) ? 64 : (MODE == 4 ? K4P : 512);
    constexpr int NC = KT / 32;
    extern __shared__ char smraw[];
    const uint32_t sbase = s2u(smraw);

    const int tid = threadIdx.x, warp = tid >> 5, lane = tid & 31;
    const int rowBase = rowOff + blockIdx.y * 128;
    const int colBase = blockIdx.x * 128;
    const int fr = tid >> 1, fks = (tid & 1) * 16;

    const f16* pA = A_ + (size_t)(rowBase + fr) * STRIDE + fks;
    const f16* pW = W_ + (size_t)(colBase + fr) * STRIDE + fks;

    const uint32_t wb = sbase + (fr * LDP + fks) * 2;
    auto ldgsts = [&](int stg, int k0) {
        const uint32_t d = wb + stg * STG;
        cp16(d,       pA + k0);  cp16(d + 16,       pA + k0 + 8);
        cp16(d + SZA, pW + k0);  cp16(d + SZA + 16, pW + k0 + 8);
        asm volatile("cp.async.commit_group;");
    };

    const int wm = warp >> 2, wn = warp & 3;     // 2x4 warps, tile 64x32
    const int la_row = lane & 15, la_sel = lane >> 4;
    const int lb_row = lane & 7;
    const int mid = lane >> 3;
    const int b_cg = (mid >> 1);
    const int b_kh = (mid & 1) * 8;

    float acc[4][4][4];
    #pragma unroll
    for (int a = 0; a < 4; a++)
        #pragma unroll
        for (int b = 0; b < 4; b++)
            #pragma unroll
            for (int c = 0; c < 4; c++) acc[a][b][c] = 0.f;

    #pragma unroll
    for (int s = 0; s < STAGES - 1 && s < NC; s++) ldgsts(s, s * 32);

    #pragma unroll
    for (int c = 0; c < NC; c++) {
        constexpr int S2 = STAGES - 2;
        const int allowed = (NC - 1 - c < S2) ? (NC - 1 - c) : S2;
        if (allowed >= 2)      asm volatile("cp.async.wait_group 2;");
        else if (allowed == 1) asm volatile("cp.async.wait_group 1;");
        else                   asm volatile("cp.async.wait_group 0;");
        __syncthreads();

        if (c + STAGES - 1 < NC) ldgsts((c + STAGES - 1) % STAGES, (c + STAGES - 1) * 32);

        const uint32_t uA = sbase + (c % STAGES) * STG;
        const uint32_t uW = uA + SZA;
        #pragma unroll
        for (int kf = 0; kf < 2; kf++) {
            const int kb = kf * 16;
            uint32_t bw[4][2];
            #pragma unroll
            for (int ntp = 0; ntp < 2; ntp++) {
                const uint32_t rb = (uint32_t)(
                    ((wn * 32 + (2 * ntp + b_cg) * 8 + lb_row) * LDP + kb + b_kh) * 2);
                uint32_t r[4];
                ldsm4(r, uW + rb);
                bw[2 * ntp][0]     = r[0];
                bw[2 * ntp][1]     = r[1];
                bw[2 * ntp + 1][0] = r[2];
                bw[2 * ntp + 1][1] = r[3];
            }
            uint32_t ah[4][4];
            #pragma unroll
            for (int mt = 0; mt < 4; mt++) {
                const uint32_t ra =
                    (uint32_t)(((wm * 64 + mt * 16 + la_row) * LDP + kb + la_sel * 8) * 2);
                ldsm4(ah[mt], uA + ra);
            }
            #pragma unroll
            for (int nt = 0; nt < 4; nt++)
                #pragma unroll
                for (int mt = 0; mt < 4; mt++)
                    mma_f16(acc[mt][nt], ah[mt], bw[nt][0], bw[nt][1]);
        }
    }

    // ---- epilogue ----
    const int g = lane >> 2, tg2 = (lane & 3) * 2;
    #pragma unroll
    for (int mt = 0; mt < 4; mt++) {
        const int row0 = rowBase + wm * 64 + mt * 16 + g;
        const int row1 = row0 + 8;
        int a0r = 0, a1r = 0;
        if constexpr (MODE == 4) { a0r = act[row0 / KO]; a1r = act[row1 / KO]; }
        #pragma unroll
        for (int nt = 0; nt < 4; nt++) {
            const int col = colBase + wn * 32 + nt * 8 + tg2;
            float v0 = acc[mt][nt][0], v1 = acc[mt][nt][1];
            float v2 = acc[mt][nt][2], v3 = acc[mt][nt][3];
            if constexpr (MODE == 0) {
                if (colBase < 512) {
                    float b0 = bias[col], b1 = bias[col + 1];
                    *(float2*)(gP + (size_t)row0 * H_ + col) = make_float2(v0 + b0, v1 + b1);
                    *(float2*)(gP + (size_t)row1 * H_ + col) = make_float2(v2 + b0, v3 + b1);
                } else {
                    int cq = col - 512;
                    *(float2*)(gQ + (size_t)row0 * H_ + cq) = make_float2(v0, v1);
                    *(float2*)(gQ + (size_t)row1 * H_ + cq) = make_float2(v2, v3);
                }
            }
            if constexpr (MODE == 2) {
                float b0 = bias[col], b1 = bias[col + 1];
                *(uint32_t*)(gH2 + (size_t)row0 * H_ + col) = pkh(v0 + b0, v1 + b1);
                *(uint32_t*)(gH2 + (size_t)row1 * H_ + col) = pkh(v2 + b0, v3 + b1);
            }
            if constexpr (MODE == 3) {
                float b0 = 9.f * bias[col], b1 = 9.f * bias[col + 1];
                *(uint32_t*)(gA4 + (size_t)row0 * K4P + 32 + col) = pkh(v0 + b0, v1 + b1);
                *(uint32_t*)(gA4 + (size_t)row1 * K4P + 32 + col) = pkh(v2 + b0, v3 + b1);
            }
            if constexpr (MODE == 4) {
                float b0 = bias[col], b1 = bias[col + 1];
                const float* r0p = nw1full + (size_t)(32 + a0r) * H_;
                const float* r1p = nw1full + (size_t)(32 + a1r) * H_;
                *(uint32_t*)(gN1 + (size_t)row0 * H_ + col) =
                    pkh(fmaxf(v0 + b0 + r0p[col], 0.f), fmaxf(v1 + b1 + r0p[col + 1], 0.f));
                *(uint32_t*)(gN1 + (size_t)row1 * H_ + col) =
                    pkh(fmaxf(v2 + b0 + r1p[col], 0.f), fmaxf(v3 + b1 + r1p[col + 1], 0.f));
            }
            if constexpr (MODE == 5) {
                float b0 = bias[col], b1 = bias[col + 1];
                *(float2*)(gN2r + (size_t)row0 * H_ + col) = make_float2(v0 + b0, v1 + b1);
                *(float2*)(gN2r + (size_t)row1 * H_ + col) = make_float2(v2 + b0, v3 + b1);
            }
        }
    }
}

// ---------------- fused: LN(gN2r)+relu -> smem -> @ nw3 + nb3 -> out ----------------
__global__ __launch_bounds__(256)
void ln2n3_k(const float* CONST g, const float* CONST bt,
             const float* CONST w3, const float* CONST b3, float* CONST out)
{
    __shared__ float xs[8][H_];
    const int tid = threadIdx.x, warp = tid >> 5, lane = tid & 31;
    const int n = blockIdx.x * 8 + warp;

    const float4* rp = (const float4*)(gN2r + (size_t)n * H_);
    float4 v[4];
    float s = 0.f, sq = 0.f;
    #pragma unroll
    for (int j = 0; j < 4; j++) {
        v[j] = rp[lane + 32 * j];
        s  += v[j].x + v[j].y + v[j].z + v[j].w;
        sq += v[j].x * v[j].x + v[j].y * v[j].y + v[j].z * v[j].z + v[j].w * v[j].w;
    }
    #pragma unroll
    for (int o = 16; o > 0; o >>= 1) {
        s  += __shfl_xor_sync(0xffffffff, s, o);
        sq += __shfl_xor_sync(0xffffffff, sq, o);
    }
    const float mean = s * (1.f / 512.f);
    const float rstd = rsqrtf(sq * (1.f / 512.f) - mean * mean + EPS);
    #pragma unroll
    for (int j = 0; j < 4; j++) {
        const int c = (lane + 32 * j) * 4;
        xs[warp][c]     = fmaxf((v[j].x - mean) * rstd * g[c]     + bt[c],     0.f);
        xs[warp][c + 1] = fmaxf((v[j].y - mean) * rstd * g[c + 1] + bt[c + 1], 0.f);
        xs[warp][c + 2] = fmaxf((v[j].z - mean) * rstd * g[c + 2] + bt[c + 2], 0.f);
        xs[warp][c + 3] = fmaxf((v[j].w - mean) * rstd * g[c + 3] + bt[c + 3], 0.f);
    }
    __syncthreads();

    const int lr = tid >> 5, c = tid & 31;
    float accv = b3[c];
    #pragma unroll 8
    for (int k = 0; k < H_; k++)
        accv = fmaf(xs[lr][k], w3[k * D_ + c], accv);
    out[(size_t)(blockIdx.x * 8 + lr) * D_ + c] = accv;
}

// ---------------- launch ----------------
extern "C" void kernel_launch(void* const* d_in, const int* in_sizes, int n_in,
                              void* d_out, int out_size)
{
    (void)in_sizes; (void)n_in; (void)out_size;
    const float* states = (const float*)d_in[0];
    const int*   action = (const int*)  d_in[1];
    const float* ew1 = (const float*)d_in[2];
    const float* eb1 = (const float*)d_in[3];
    const float* ew2 = (const float*)d_in[4];
    const float* eb2 = (const float*)d_in[5];
    const float* eg  = (const float*)d_in[6];
    const float* ebt = (const float*)d_in[7];
    const float* ew3 = (const float*)d_in[8];
    const float* eb3 = (const float*)d_in[9];
    const float* nw1 = (const float*)d_in[10];
    const float* nb1 = (const float*)d_in[11];
    const float* nw2 = (const float*)d_in[12];
    const float* nb2 = (const float*)d_in[13];
    const float* ng  = (const float*)d_in[14];
    const float* nbt = (const float*)d_in[15];
    const float* nw3 = (const float*)d_in[16];
    const float* nb3 = (const float*)d_in[17];
    float* out = (float*)d_out;

    static bool attrSet = false;
    if (!attrSet) {
        cudaFuncSetAttribute(tg<0>, cudaFuncAttributeMaxDynamicSharedMemorySize, SMEM_SZ);
        cudaFuncSetAttribute(tg<2>, cudaFuncAttributeMaxDynamicSharedMemorySize, SMEM_SZ);
        cudaFuncSetAttribute(tg<3>, cudaFuncAttributeMaxDynamicSharedMemorySize, SMEM_SZ);
        cudaFuncSetAttribute(tg<4>, cudaFuncAttributeMaxDynamicSharedMemorySize, SMEM_SZ);
        cudaFuncSetAttribute(tg<5>, cudaFuncAttributeMaxDynamicSharedMemorySize, SMEM_SZ);
        attrSet = true;
    }

    f16 *w0, *w2, *w3w, *w4, *w5, *st, *e, *sS, *a4, *n1;
    cudaGetSymbolAddress((void**)&w0, gW0);
    cudaGetSymbolAddress((void**)&w2, gW2);
    cudaGetSymbolAddress((void**)&w3w, gW3);
    cudaGetSymbolAddress((void**)&w4, gW4);
    cudaGetSymbolAddress((void**)&w5, gW5);
    cudaGetSymbolAddress((void**)&st, gST);
    cudaGetSymbolAddress((void**)&e,  gE);
    cudaGetSymbolAddress((void**)&sS, gS);
    cudaGetSymbolAddress((void**)&a4, gA4);
    cudaGetSymbolAddress((void**)&n1, gN1);

    prep_all<<<(PREP_N + 255) / 256, 256>>>(ew1, ew2, ew3, nw1, nw2, states);

    dim3 blk(256);
    tg<0><<<dim3(8, NN / 128), blk, SMEM_SZ>>>(st, w0, eb1, nullptr, nullptr, 0,
                                               NN / 128, 0, 0, nullptr, nullptr);

    // slice 0 edge-A materialization
    esplit<<<ESL * 64 / 256, 256>>>(0);

    // X0: tg2(slice0) + side esplit(slice1): 720 esplit rows (2880 blocks x 16 edges)
    tg<2><<<dim3(4, ESL / 128 + ESL / 16 / 4), blk, SMEM_SZ>>>(
        e, w2, eb2, nullptr, nullptr, 0,
        ESL / 128, 1, ESL, nullptr, nullptr);

    // X1: tg2(slice1) + side ln_sum(slice0): 160 rows (640 blocks x 8 nodes)
    tg<2><<<dim3(4, ESL / 128 + NSL / 8 / 4), blk, SMEM_SZ>>>(
        e, w2, eb2, nullptr, nullptr, ESL,
        ESL / 128, 2, 0, eg, ebt);

    // slice 1 ln_sum
    ln_sum_k<<<NSL / 8, 256>>>(eg, ebt, NSL);

    tg<3><<<dim3(4, NN / 128), blk, SMEM_SZ>>>(sS, w3w, eb3, nullptr, nullptr, 0,
                                               NN / 128, 0, 0, nullptr, nullptr);
    tg<4><<<dim3(4, NN / 128), blk, SMEM_SZ>>>(a4, w4, nb1, action, nw1, 0,
                                               NN / 128, 0, 0, nullptr, nullptr);
    tg<5><<<dim3(4, NN / 128), blk, SMEM_SZ>>>(n1, w5, nb2, nullptr, nullptr, 0,
                                               NN / 128, 0, 0, nullptr, nullptr);
    ln2n3_k<<<NN / 8, 256>>>(ng, nbt, nw3, nb3, out);
}

// round 17
// speedup vs baseline: 1.1160x; 1.1160x over previous
#include <cuda_runtime.h>
#include <cuda_fp16.h>
#include <cstdint>

#define CONST __restrict__
using f16 = __half;

static constexpr int B_  = 1024;
static constexpr int KO  = 10;
static constexpr int D_  = 32;
static constexpr int H_  = 512;
static constexpr int NN  = B_ * KO;     // 10240
static constexpr int EPN = KO - 1;      // 9
static constexpr int NE  = NN * EPN;    // 92160
static constexpr float EPS = 1e-5f;
static constexpr int K4P = 576;

// ---------------- scratch ----------------
__device__ __align__(16) f16 gST[NN * 64];
__device__ float gP[NN * H_], gQ[NN * H_];
__device__ __align__(16) f16 gE[(size_t)NE * H_];
__device__ __align__(16) f16 gH2[(size_t)NE * H_];
__device__ __align__(16) f16 gS [NN * H_];
__device__ __align__(16) f16 gA4[NN * K4P];
__device__ __align__(16) f16 gN1[NN * H_];
__device__ float gN2r[NN * H_];

__device__ __align__(16) f16 gW0[1024 * 64];
__device__ __align__(16) f16 gW2[H_ * H_];
__device__ __align__(16) f16 gW3[H_ * H_];
__device__ __align__(16) f16 gW4[H_ * K4P];
__device__ __align__(16) f16 gW5[H_ * H_];

// ---------------- helpers ----------------
__device__ __forceinline__ uint32_t s2u(const void* p) {
    uint32_t a;
    asm("{ .reg .u64 t; cvta.to.shared.u64 t, %1; cvt.u32.u64 %0, t; }" : "=r"(a) : "l"(p));
    return a;
}
__device__ __forceinline__ void cp16(uint32_t s, const void* g) {
    asm volatile("cp.async.cg.shared.global [%0], [%1], 16;" :: "r"(s), "l"(g));
}
__device__ __forceinline__ void ldsm4(uint32_t* r, uint32_t a) {
    asm volatile("ldmatrix.sync.aligned.m8n8.x4.shared.b16 {%0,%1,%2,%3}, [%4];"
        : "=r"(r[0]), "=r"(r[1]), "=r"(r[2]), "=r"(r[3]) : "r"(a));
}
__device__ __forceinline__ void mma_f16(float* c, const uint32_t* a, uint32_t b0, uint32_t b1) {
    asm("mma.sync.aligned.m16n8k16.row.col.f32.f16.f16.f32 "
        "{%0,%1,%2,%3}, {%4,%5,%6,%7}, {%8,%9}, {%0,%1,%2,%3};\n"
        : "+f"(c[0]), "+f"(c[1]), "+f"(c[2]), "+f"(c[3])
        : "r"(a[0]), "r"(a[1]), "r"(a[2]), "r"(a[3]), "r"(b0), "r"(b1));
}
__device__ __forceinline__ uint32_t pkh(float a, float b) {
    __half2 t; t.x = __float2half_rn(a); t.y = __float2half_rn(b);
    return *(uint32_t*)&t;
}

// ---------------- merged prep ----------------
static constexpr int PREP_N = 1425408;

__global__ void prep_all(const float* CONST ew1, const float* CONST ew2,
                         const float* CONST ew3, const float* CONST nw1,
                         const float* CONST nw2, const float* CONST states)
{
    int idx = blockIdx.x * 256 + threadIdx.x;
    if (idx >= PREP_N) return;
    if (idx < 32768) {
        int k = idx & 31, n = idx >> 5;
        int sr = (n < 512) ? k : 32 + k;
        int sn = (n < 512) ? n : n - 512;
        gW0[n * 64 + k] = __float2half_rn(ew1[(size_t)sr * H_ + sn]);
    } else if (idx < 294912) {
        int i2 = idx - 32768;
        int k = i2 & 511, n = i2 >> 9;
        gW2[i2] = __float2half_rn(ew2[(size_t)k * H_ + n]);
    } else if (idx < 557056) {
        int i2 = idx - 294912;
        int k = i2 & 511, n = i2 >> 9;
        gW3[i2] = __float2half_rn(ew3[(size_t)k * H_ + n]);
    } else if (idx < 835584) {
        int i2 = idx - 557056;
        int k = i2 % 544, n = i2 / 544;
        int sr = (k >= 32) ? k + 4 : k;
        gW4[n * K4P + k] = __float2half_rn(nw1[(size_t)sr * H_ + n]);
    } else if (idx < 1097728) {
        int i2 = idx - 835584;
        int k = i2 & 511, n = i2 >> 9;
        gW5[i2] = __float2half_rn(nw2[(size_t)k * H_ + n]);
    } else {
        int i2 = idx - 1097728;
        int r = i2 >> 5, c = i2 & 31;
        f16 h = __float2half_rn(states[i2]);
        gST[r * 64 + c] = h;
        gA4[r * K4P + c] = h;
    }
}

// ---------------- edge A: relu(P+Q) -> fp16 plane ----------------
__global__ __launch_bounds__(256) void esplit(int edgeOff)
{
    int gi = blockIdx.x * 256 + threadIdx.x;
    int e = edgeOff + (gi >> 6);
    int cg = (gi & 63) * 8;
    int node = e / EPN;
    int jj = e - node * EPN;
    int i = node % KO;
    int j = jj + (jj >= i ? 1 : 0);
    int cn = node - i + j;

    float4 p0 = *(const float4*)(gP + (size_t)node * H_ + cg);
    float4 p1 = *(const float4*)(gP + (size_t)node * H_ + cg + 4);
    float4 q0 = *(const float4*)(gQ + (size_t)cn * H_ + cg);
    float4 q1 = *(const float4*)(gQ + (size_t)cn * H_ + cg + 4);
    f16 o[8];
    o[0] = __float2half_rn(fmaxf(p0.x + q0.x, 0.f));
    o[1] = __float2half_rn(fmaxf(p0.y + q0.y, 0.f));
    o[2] = __float2half_rn(fmaxf(p0.z + q0.z, 0.f));
    o[3] = __float2half_rn(fmaxf(p0.w + q0.w, 0.f));
    o[4] = __float2half_rn(fmaxf(p1.x + q1.x, 0.f));
    o[5] = __float2half_rn(fmaxf(p1.y + q1.y, 0.f));
    o[6] = __float2half_rn(fmaxf(p1.z + q1.z, 0.f));
    o[7] = __float2half_rn(fmaxf(p1.w + q1.w, 0.f));
    *(uint4*)(gE + (size_t)e * H_ + cg) = *(const uint4*)o;
}

// ---------------- fp16 mma GEMM, BK=32, 4-stage pipeline, B via ldsm4 ----------------
static constexpr int LDP = 40;
static constexpr int SZA = 128 * LDP * 2;    // 10240 B
static constexpr int STG = 2 * SZA;          // 20480 B per stage
static constexpr int STAGES = 4;
static constexpr int SMEM_SZ = STAGES * STG; // 81920 B

template <int MODE>
__global__ __launch_bounds__(256, 2)
void tg(const f16* CONST A_, const f16* CONST W_,
        const float* CONST bias, const int* CONST act,
        const float* CONST nw1full, int rowOff)
{
    constexpr int KT     = (MODE == 0) ? 32 : (MODE == 4 ? 544 : 512);
    constexpr int STRIDE = (MODE == 0) ? 64 : (MODE == 4 ? K4P : 512);
    constexpr int NC = KT / 32;
    extern __shared__ char smraw[];
    const uint32_t sbase = s2u(smraw);

    const int tid = threadIdx.x, warp = tid >> 5, lane = tid & 31;
    const int rowBase = rowOff + blockIdx.y * 128;
    const int colBase = blockIdx.x * 128;
    const int fr = tid >> 1, fks = (tid & 1) * 16;

    const f16* pA = A_ + (size_t)(rowBase + fr) * STRIDE + fks;
    const f16* pW = W_ + (size_t)(colBase + fr) * STRIDE + fks;

    const uint32_t wb = sbase + (fr * LDP + fks) * 2;
    auto ldgsts = [&](int stg, int k0) {
        const uint32_t d = wb + stg * STG;
        cp16(d,       pA + k0);  cp16(d + 16,       pA + k0 + 8);
        cp16(d + SZA, pW + k0);  cp16(d + SZA + 16, pW + k0 + 8);
        asm volatile("cp.async.commit_group;");
    };

    const int wm = warp >> 2, wn = warp & 3;     // 2x4 warps, tile 64x32
    const int la_row = lane & 15, la_sel = lane >> 4;
    const int lb_row = lane & 7;
    const int mid = lane >> 3;
    const int b_cg = (mid >> 1);
    const int b_kh = (mid & 1) * 8;

    float acc[4][4][4];
    #pragma unroll
    for (int a = 0; a < 4; a++)
        #pragma unroll
        for (int b = 0; b < 4; b++)
            #pragma unroll
            for (int c = 0; c < 4; c++) acc[a][b][c] = 0.f;

    #pragma unroll
    for (int s = 0; s < STAGES - 1 && s < NC; s++) ldgsts(s, s * 32);

    #pragma unroll
    for (int c = 0; c < NC; c++) {
        constexpr int S2 = STAGES - 2;
        const int allowed = (NC - 1 - c < S2) ? (NC - 1 - c) : S2;
        if (allowed >= 2)      asm volatile("cp.async.wait_group 2;");
        else if (allowed == 1) asm volatile("cp.async.wait_group 1;");
        else                   asm volatile("cp.async.wait_group 0;");
        __syncthreads();

        if (c + STAGES - 1 < NC) ldgsts((c + STAGES - 1) % STAGES, (c + STAGES - 1) * 32);

        const uint32_t uA = sbase + (c % STAGES) * STG;
        const uint32_t uW = uA + SZA;
        #pragma unroll
        for (int kf = 0; kf < 2; kf++) {
            const int kb = kf * 16;
            uint32_t bw[4][2];
            #pragma unroll
            for (int ntp = 0; ntp < 2; ntp++) {
                const uint32_t rb = (uint32_t)(
                    ((wn * 32 + (2 * ntp + b_cg) * 8 + lb_row) * LDP + kb + b_kh) * 2);
                uint32_t r[4];
                ldsm4(r, uW + rb);
                bw[2 * ntp][0]     = r[0];
                bw[2 * ntp][1]     = r[1];
                bw[2 * ntp + 1][0] = r[2];
                bw[2 * ntp + 1][1] = r[3];
            }
            uint32_t ah[4][4];
            #pragma unroll
            for (int mt = 0; mt < 4; mt++) {
                const uint32_t ra =
                    (uint32_t)(((wm * 64 + mt * 16 + la_row) * LDP + kb + la_sel * 8) * 2);
                ldsm4(ah[mt], uA + ra);
            }
            #pragma unroll
            for (int nt = 0; nt < 4; nt++)
                #pragma unroll
                for (int mt = 0; mt < 4; mt++)
                    mma_f16(acc[mt][nt], ah[mt], bw[nt][0], bw[nt][1]);
        }
    }

    // ---- epilogue ----
    const int g = lane >> 2, tg2 = (lane & 3) * 2;
    #pragma unroll
    for (int mt = 0; mt < 4; mt++) {
        const int row0 = rowBase + wm * 64 + mt * 16 + g;
        const int row1 = row0 + 8;
        int a0r = 0, a1r = 0;
        if constexpr (MODE == 4) { a0r = act[row0 / KO]; a1r = act[row1 / KO]; }
        #pragma unroll
        for (int nt = 0; nt < 4; nt++) {
            const int col = colBase + wn * 32 + nt * 8 + tg2;
            float v0 = acc[mt][nt][0], v1 = acc[mt][nt][1];
            float v2 = acc[mt][nt][2], v3 = acc[mt][nt][3];
            if constexpr (MODE == 0) {
                if (colBase < 512) {
                    float b0 = bias[col], b1 = bias[col + 1];
                    *(float2*)(gP + (size_t)row0 * H_ + col) = make_float2(v0 + b0, v1 + b1);
                    *(float2*)(gP + (size_t)row1 * H_ + col) = make_float2(v2 + b0, v3 + b1);
                } else {
                    int cq = col - 512;
                    *(float2*)(gQ + (size_t)row0 * H_ + cq) = make_float2(v0, v1);
                    *(float2*)(gQ + (size_t)row1 * H_ + cq) = make_float2(v2, v3);
                }
            }
            if constexpr (MODE == 2) {
                float b0 = bias[col], b1 = bias[col + 1];
                *(uint32_t*)(gH2 + (size_t)row0 * H_ + col) = pkh(v0 + b0, v1 + b1);
                *(uint32_t*)(gH2 + (size_t)row1 * H_ + col) = pkh(v2 + b0, v3 + b1);
            }
            if constexpr (MODE == 3) {
                float b0 = 9.f * bias[col], b1 = 9.f * bias[col + 1];
                *(uint32_t*)(gA4 + (size_t)row0 * K4P + 32 + col) = pkh(v0 + b0, v1 + b1);
                *(uint32_t*)(gA4 + (size_t)row1 * K4P + 32 + col) = pkh(v2 + b0, v3 + b1);
            }
            if constexpr (MODE == 4) {
                float b0 = bias[col], b1 = bias[col + 1];
                const float* r0p = nw1full + (size_t)(32 + a0r) * H_;
                const float* r1p = nw1full + (size_t)(32 + a1r) * H_;
                *(uint32_t*)(gN1 + (size_t)row0 * H_ + col) =
                    pkh(fmaxf(v0 + b0 + r0p[col], 0.f), fmaxf(v1 + b1 + r0p[col + 1], 0.f));
                *(uint32_t*)(gN1 + (size_t)row1 * H_ + col) =
                    pkh(fmaxf(v2 + b0 + r1p[col], 0.f), fmaxf(v3 + b1 + r1p[col + 1], 0.f));
            }
            if constexpr (MODE == 5) {
                float b0 = bias[col], b1 = bias[col + 1];
                *(float2*)(gN2r + (size_t)row0 * H_ + col) = make_float2(v0 + b0, v1 + b1);
                *(float2*)(gN2r + (size_t)row1 * H_ + col) = make_float2(v2 + b0, v3 + b1);
            }
        }
    }
}

// ---------------- LN + relu + 9-row sum over fp16 gH2 -> fp16 S ----------------
__global__ __launch_bounds__(256)
void ln_sum_k(const float* CONST g, const float* CONST bt, int nodeOff)
{
    const int tid = threadIdx.x, warp = tid >> 5, lane = tid & 31;
    const int n = nodeOff + blockIdx.x * 8 + warp;

    float G[16], Bt[16], acc[16];
    #pragma unroll
    for (int j = 0; j < 2; j++) {
        const int cb = (lane + 32 * j) * 8;
        #pragma unroll
        for (int u = 0; u < 8; u++) {
            G[j * 8 + u] = g[cb + u];
            Bt[j * 8 + u] = bt[cb + u];
            acc[j * 8 + u] = 0.f;
        }
    }

    for (int e = 0; e < EPN; e++) {
        const f16* rp = gH2 + (size_t)(n * EPN + e) * H_;
        float v[16];
        float s = 0.f, sq = 0.f;
        #pragma unroll
        for (int j = 0; j < 2; j++) {
            uint4 raw = *(const uint4*)(rp + (lane + 32 * j) * 8);
            const __half2* h2 = (const __half2*)&raw;
            #pragma unroll
            for (int p = 0; p < 4; p++) {
                float2 f2 = __half22float2(h2[p]);
                v[j * 8 + p * 2]     = f2.x;
                v[j * 8 + p * 2 + 1] = f2.y;
            }
        }
        #pragma unroll
        for (int u = 0; u < 16; u++) { s += v[u]; sq += v[u] * v[u]; }
        #pragma unroll
        for (int o = 16; o > 0; o >>= 1) {
            s  += __shfl_xor_sync(0xffffffff, s, o);
            sq += __shfl_xor_sync(0xffffffff, sq, o);
        }
        const float mean = s * (1.f / 512.f);
        const float rstd = rsqrtf(sq * (1.f / 512.f) - mean * mean + EPS);
        #pragma unroll
        for (int u = 0; u < 16; u++)
            acc[u] += fmaxf((v[u] - mean) * rstd * G[u] + Bt[u], 0.f);
    }

    #pragma unroll
    for (int j = 0; j < 2; j++) {
        const int cb = (lane + 32 * j) * 8;
        uint4 o4;
        o4.x = pkh(acc[j * 8 + 0], acc[j * 8 + 1]);
        o4.y = pkh(acc[j * 8 + 2], acc[j * 8 + 3]);
        o4.z = pkh(acc[j * 8 + 4], acc[j * 8 + 5]);
        o4.w = pkh(acc[j * 8 + 6], acc[j * 8 + 7]);
        *(uint4*)(gS + (size_t)n * H_ + cb) = o4;
    }
}

// ---------------- fused: LN(gN2r)+relu -> smem -> @ nw3 + nb3 -> out ----------------
__global__ __launch_bounds__(256)
void ln2n3_k(const float* CONST g, const float* CONST bt,
             const float* CONST w3, const float* CONST b3, float* CONST out)
{
    __shared__ float xs[8][H_];
    const int tid = threadIdx.x, warp = tid >> 5, lane = tid & 31;
    const int n = blockIdx.x * 8 + warp;

    const float4* rp = (const float4*)(gN2r + (size_t)n * H_);
    float4 v[4];
    float s = 0.f, sq = 0.f;
    #pragma unroll
    for (int j = 0; j < 4; j++) {
        v[j] = rp[lane + 32 * j];
        s  += v[j].x + v[j].y + v[j].z + v[j].w;
        sq += v[j].x * v[j].x + v[j].y * v[j].y + v[j].z * v[j].z + v[j].w * v[j].w;
    }
    #pragma unroll
    for (int o = 16; o > 0; o >>= 1) {
        s  += __shfl_xor_sync(0xffffffff, s, o);
        sq += __shfl_xor_sync(0xffffffff, sq, o);
    }
    const float mean = s * (1.f / 512.f);
    const float rstd = rsqrtf(sq * (1.f / 512.f) - mean * mean + EPS);
    #pragma unroll
    for (int j = 0; j < 4; j++) {
        const int c = (lane + 32 * j) * 4;
        xs[warp][c]     = fmaxf((v[j].x - mean) * rstd * g[c]     + bt[c],     0.f);
        xs[warp][c + 1] = fmaxf((v[j].y - mean) * rstd * g[c + 1] + bt[c + 1], 0.f);
        xs[warp][c + 2] = fmaxf((v[j].z - mean) * rstd * g[c + 2] + bt[c + 2], 0.f);
        xs[warp][c + 3] = fmaxf((v[j].w - mean) * rstd * g[c + 3] + bt[c + 3], 0.f);
    }
    __syncthreads();

    const int lr = tid >> 5, c = tid & 31;
    float accv = b3[c];
    #pragma unroll 8
    for (int k = 0; k < H_; k++)
        accv = fmaf(xs[lr][k], w3[k * D_ + c], accv);
    out[(size_t)(blockIdx.x * 8 + lr) * D_ + c] = accv;
}

// ---------------- launch ----------------
extern "C" void kernel_launch(void* const* d_in, const int* in_sizes, int n_in,
                              void* d_out, int out_size)
{
    (void)in_sizes; (void)n_in; (void)out_size;
    const float* states = (const float*)d_in[0];
    const int*   action = (const int*)  d_in[1];
    const float* ew1 = (const float*)d_in[2];
    const float* eb1 = (const float*)d_in[3];
    const float* ew2 = (const float*)d_in[4];
    const float* eb2 = (const float*)d_in[5];
    const float* eg  = (const float*)d_in[6];
    const float* ebt = (const float*)d_in[7];
    const float* ew3 = (const float*)d_in[8];
    const float* eb3 = (const float*)d_in[9];
    const float* nw1 = (const float*)d_in[10];
    const float* nb1 = (const float*)d_in[11];
    const float* nw2 = (const float*)d_in[12];
    const float* nb2 = (const float*)d_in[13];
    const float* ng  = (const float*)d_in[14];
    const float* nbt = (const float*)d_in[15];
    const float* nw3 = (const float*)d_in[16];
    const float* nb3 = (const float*)d_in[17];
    float* out = (float*)d_out;

    static bool attrSet = false;
    if (!attrSet) {
        cudaFuncSetAttribute(tg<0>, cudaFuncAttributeMaxDynamicSharedMemorySize, SMEM_SZ);
        cudaFuncSetAttribute(tg<2>, cudaFuncAttributeMaxDynamicSharedMemorySize, SMEM_SZ);
        cudaFuncSetAttribute(tg<3>, cudaFuncAttributeMaxDynamicSharedMemorySize, SMEM_SZ);
        cudaFuncSetAttribute(tg<4>, cudaFuncAttributeMaxDynamicSharedMemorySize, SMEM_SZ);
        cudaFuncSetAttribute(tg<5>, cudaFuncAttributeMaxDynamicSharedMemorySize, SMEM_SZ);
        attrSet = true;
    }

    f16 *w0, *w2, *w3w, *w4, *w5, *st, *e, *sS, *a4, *n1;
    cudaGetSymbolAddress((void**)&w0, gW0);
    cudaGetSymbolAddress((void**)&w2, gW2);
    cudaGetSymbolAddress((void**)&w3w, gW3);
    cudaGetSymbolAddress((void**)&w4, gW4);
    cudaGetSymbolAddress((void**)&w5, gW5);
    cudaGetSymbolAddress((void**)&st, gST);
    cudaGetSymbolAddress((void**)&e,  gE);
    cudaGetSymbolAddress((void**)&sS, gS);
    cudaGetSymbolAddress((void**)&a4, gA4);
    cudaGetSymbolAddress((void**)&n1, gN1);

    prep_all<<<(PREP_N + 255) / 256, 256>>>(ew1, ew2, ew3, nw1, nw2, states);

    dim3 blk(256);
    tg<0><<<dim3(8, NN / 128), blk, SMEM_SZ>>>(st, w0, eb1, nullptr, nullptr, 0);

    // single-slice edge pipeline: esplit -> big GEMM -> ln_sum
    esplit<<<NE * 64 / 256, 256>>>(0);
    tg<2><<<dim3(4, NE / 128), blk, SMEM_SZ>>>(e, w2, eb2, nullptr, nullptr, 0);
    ln_sum_k<<<NN / 8, 256>>>(eg, ebt, 0);

    tg<3><<<dim3(4, NN / 128), blk, SMEM_SZ>>>(sS, w3w, eb3, nullptr, nullptr, 0);
    tg<4><<<dim3(4, NN / 128), blk, SMEM_SZ>>>(a4, w4, nb1, action, nw1, 0);
    tg<5><<<dim3(4, NN / 128), blk, SMEM_SZ>>>(n1, w5, nb2, nullptr, nullptr, 0);
    ln2n3_k<<<NN / 8, 256>>>(ng, nbt, nw3, nb3, out);
}